// round 16
// baseline (speedup 1.0000x reference)
#include <cuda_runtime.h>

#define T_STEPS 20
#define HW4 57600               // float4 per (b,t) slab
#define SLAB1OFF4 (20*HW4)      // float4 offset of batch-1 slab (same t)
#define NPB 22                  // 22*20 = 440 <= 444 = 148 SMs * 3 blocks: one wave
#define TPB 256
#define STRIDE (NPB*TPB)        // 5632 -> <=11 iters, <=88 elems/thread (<128: fields exact)
#define NACC 26
// g_part row: 0:cnt 1:S1P 2:S1Q 3:S2P 4:S2Q 5:SPQ (P=31^pn raw moments, nz-masked)
// 6..10:ptot_cum 11..15:ttot_cum 16..20:hits_cum 21..25:mae_cum

__device__ float        g_part[T_STEPS * NPB * NACC];
__device__ unsigned int g_ticket;

__constant__ float c_tw[T_STEPS] = {
    0.0075f, 0.02f, 0.03f, 0.04f, 0.05f, 0.06f, 0.07f, 0.08f, 0.09f, 0.1f,
    0.09f,   0.08f, 0.07f, 0.06f, 0.05f, 0.04f, 0.03f, 0.02f, 0.0075f, 0.005f};

// thresholds in normalized space: ln(1+thr)/ln(31)
#define C0 0.02775496f
#define C1 0.20184909f
#define C2 0.31992323f
#define C3 0.52177232f
#define C4 0.63984647f

__device__ __forceinline__ float fge(float a, float b) {
    float r; asm("set.ge.f32.f32 %0, %1, %2;" : "=f"(r) : "f"(a), "f"(b)); return r;
}

struct Acc {
    float cnt, s1p, s1t, s2p, s2t, spt;
    float ptA, ptB;   // packed cumulative ptot: A = l0 +128*l1 +16384*l2, B = l3 +128*l4
    float ttA, ttB;
    float hA,  hB;    // packed cumulative hits
    float m0, m1, m2, m3, m4;   // cumulative mae
};

__device__ __forceinline__ void accum_one(float pn, float tn, float mm, Acc& a) {
    const float K = 4.954196310386875f;   // log2(31)
    float P, Q;                           // P = 31^pn
    asm("ex2.approx.f32 %0, %1;" : "=f"(P) : "f"(pn * K));
    asm("ex2.approx.f32 %0, %1;" : "=f"(Q) : "f"(tn * K));

    // predicate-free sentinel: mm = (mk-0.5)*1e10.
    // mk>0.5 -> mm >= 600 > pn -> min passes value; mk<=0.5 -> mm <= 0 -> fails all C_l
    float pnm = fminf(pn, mm);
    float tnm = fminf(tn, mm);

    float a0 = fge(pnm, C0), a1 = fge(pnm, C1), a2 = fge(pnm, C2),
          a3 = fge(pnm, C3), a4 = fge(pnm, C4);
    float b0 = fge(tnm, C0), b1 = fge(tnm, C1), b2 = fge(tnm, C2),
          b3 = fge(tnm, C3), b4 = fge(tnm, C4);

    // packed indicator words (exact: fields <= 88 < 128, total < 2^24)
    float wpA = fmaf(a2, 16384.0f, fmaf(a1, 128.0f, a0));
    float wpB = fmaf(a4, 128.0f, a3);
    float wtA = fmaf(b2, 16384.0f, fmaf(b1, 128.0f, b0));
    float wtB = fmaf(b4, 128.0f, b3);
    a.ptA += wpA; a.ptB += wpB;
    a.ttA += wtA; a.ttB += wtB;

    // eq = (cp == ct): indicator-pair equality, fused XOR|OR LOP3 tree (bit-exact)
    unsigned u01 = (__float_as_uint(a0) ^ __float_as_uint(b0))
                 | (__float_as_uint(a1) ^ __float_as_uint(b1));
    unsigned u23 = (__float_as_uint(a2) ^ __float_as_uint(b2))
                 | (__float_as_uint(a3) ^ __float_as_uint(b3));
    unsigned u   = u01 | u23 | (__float_as_uint(a4) ^ __float_as_uint(b4));
    float eq = 1.0f - __uint_as_float(u);      // u is 0 or 0x3F800000 (=1.0f)
    a.hA = fmaf(eq, wpA, a.hA);
    a.hB = fmaf(eq, wpB, a.hB);

    // nz = masked & not double-zero (bit-OR of 0/1.0f patterns)
    float orf = __uint_as_float(__float_as_uint(a0) | __float_as_uint(b0));
    float Pm = P * orf;
    float Qm = Q * orf;
    a.cnt += orf;
    a.s1p += Pm;
    a.s1t += Qm;
    a.s2p = fmaf(Pm, P, a.s2p);
    a.s2t = fmaf(Qm, Q, a.s2t);
    a.spt = fmaf(Pm, Q, a.spt);

    // cumulative mae (mask rides on b_l)
    float d = fabsf(P - Q);
    a.m0 = fmaf(b0, d, a.m0);
    a.m1 = fmaf(b1, d, a.m1);
    a.m2 = fmaf(b2, d, a.m2);
    a.m3 = fmaf(b3, d, a.m3);
    a.m4 = fmaf(b4, d, a.m4);
}

__device__ __forceinline__ void accum4(const float4& pv, const float4& tv,
                                       const float4& mv, Acc& a) {
    const float BIGM = 1.0e10f;
    accum_one(pv.x, tv.x, (mv.x - 0.5f) * BIGM, a);
    accum_one(pv.y, tv.y, (mv.y - 0.5f) * BIGM, a);
    accum_one(pv.z, tv.z, (mv.z - 0.5f) * BIGM, a);
    accum_one(pv.w, tv.w, (mv.w - 0.5f) * BIGM, a);
}

// exact unpack of base-128 packed integer-valued floats
__device__ __forceinline__ void unpack3(float v, float& c0, float& c1, float& c2) {
    c2 = floorf(v * (1.0f / 16384.0f));
    float rem = v - c2 * 16384.0f;
    c1 = floorf(rem * (1.0f / 128.0f));
    c0 = rem - c1 * 128.0f;
}
__device__ __forceinline__ void unpack2(float v, float& c0, float& c1) {
    c1 = floorf(v * (1.0f / 128.0f));
    c0 = v - c1 * 128.0f;
}

__global__ __launch_bounds__(TPB, 3) void k_fused(const float* __restrict__ pred,
                                                  const float* __restrict__ targ,
                                                  const float* __restrict__ mask,
                                                  float* __restrict__ out) {
    const int t   = blockIdx.y;
    const int gid = blockIdx.x * TPB + threadIdx.x;

    Acc a;
    a.cnt = a.s1p = a.s1t = a.s2p = a.s2t = a.spt = 0.0f;
    a.ptA = a.ptB = a.ttA = a.ttB = a.hA = a.hB = 0.0f;
    a.m0 = a.m1 = a.m2 = a.m3 = a.m4 = 0.0f;

    const size_t base4 = (size_t)t * HW4;
    const float4* p4  = (const float4*)pred + base4;
    const float4* t4  = (const float4*)targ + base4;
    const float4* m4  = (const float4*)mask + base4;
    const float4* p4b = p4 + SLAB1OFF4;
    const float4* t4b = t4 + SLAB1OFF4;
    const float4* m4b = m4 + SLAB1OFF4;

    // 1-deep, 6-load software pipeline; unroll 2 lets ptxas rename the
    // ping-pong buffers (eliminates 24 rotation MOVs per iteration)
    float4 pv0 = __ldcs(p4  + gid);
    float4 tv0 = __ldcs(t4  + gid);
    float4 mv0 = __ldcs(m4  + gid);
    float4 pv1 = __ldcs(p4b + gid);
    float4 tv1 = __ldcs(t4b + gid);
    float4 mv1 = __ldcs(m4b + gid);

#pragma unroll 2
    for (int v = gid + STRIDE; v < HW4; v += STRIDE) {
        float4 npv0 = __ldcs(p4  + v);
        float4 ntv0 = __ldcs(t4  + v);
        float4 nmv0 = __ldcs(m4  + v);
        float4 npv1 = __ldcs(p4b + v);
        float4 ntv1 = __ldcs(t4b + v);
        float4 nmv1 = __ldcs(m4b + v);
        accum4(pv0, tv0, mv0, a);
        accum4(pv1, tv1, mv1, a);
        pv0 = npv0; tv0 = ntv0; mv0 = nmv0;
        pv1 = npv1; tv1 = ntv1; mv1 = nmv1;
    }
    accum4(pv0, tv0, mv0, a);
    accum4(pv1, tv1, mv1, a);

    // unpack packed counters (exact) -> 26 partials
    float acc[NACC];
    acc[0] = a.cnt;
    acc[1] = a.s1p; acc[2] = a.s1t; acc[3] = a.s2p; acc[4] = a.s2t; acc[5] = a.spt;
    unpack3(a.ptA, acc[6],  acc[7],  acc[8]);  unpack2(a.ptB, acc[9],  acc[10]);
    unpack3(a.ttA, acc[11], acc[12], acc[13]); unpack2(a.ttB, acc[14], acc[15]);
    unpack3(a.hA,  acc[16], acc[17], acc[18]); unpack2(a.hB,  acc[19], acc[20]);
    acc[21] = a.m0; acc[22] = a.m1; acc[23] = a.m2; acc[24] = a.m3; acc[25] = a.m4;

    // deterministic warp tree reduce
#pragma unroll
    for (int i = 0; i < NACC; i++) {
#pragma unroll
        for (int o = 16; o > 0; o >>= 1)
            acc[i] += __shfl_xor_sync(0xffffffffu, acc[i], o);
    }

    __shared__ float s[TPB / 32][NACC];
    int w = threadIdx.x >> 5, ln = threadIdx.x & 31;
    if (ln == 0) {
#pragma unroll
        for (int i = 0; i < NACC; i++) s[w][i] = acc[i];
    }
    __syncthreads();
    if (threadIdx.x < NACC) {
        float vv = 0.0f;
#pragma unroll
        for (int w2 = 0; w2 < TPB / 32; w2++) vv += s[w2][threadIdx.x];
        g_part[((size_t)t * NPB + blockIdx.x) * NACC + threadIdx.x] = vv;
    }

    // ---- last block finishes (deterministic: reads fixed g_part) ----
    __threadfence();
    __syncthreads();
    __shared__ bool amLast;
    if (threadIdx.x == 0) {
        unsigned done = atomicAdd(&g_ticket, 1u);
        amLast = (done == (unsigned)(NPB * T_STEPS - 1));
    }
    __syncthreads();
    if (!amLast) return;
    __threadfence();

    __shared__ double sd[T_STEPS][NACC];
    for (int idx2 = threadIdx.x; idx2 < T_STEPS * NACC; idx2 += TPB) {
        int tt = idx2 / NACC, j = idx2 % NACC;
        double vv = 0.0;
#pragma unroll 11
        for (int k = 0; k < NPB; k++)
            vv += (double)g_part[((size_t)tt * NPB + k) * NACC + j];
        sd[tt][j] = vv;
    }
    __syncthreads();

    __shared__ float sts[T_STEPS][5], sma[T_STEPS][5], ssc[T_STEPS];
    if (threadIdx.x < T_STEPS) {
        int tt = threadIdx.x;
        double C   = sd[tt][0];
        double S1P = sd[tt][1], S1Q = sd[tt][2];
        double S2P = sd[tt][3], S2Q = sd[tt][4], SPQ = sd[tt][5];
        // shift: p = P-1, q = Q-1 on the nz-masked set of size C
        double S1p = S1P - C, S1t = S1Q - C;
        double S2p = S2P - 2.0 * S1P + C;
        double S2t = S2Q - 2.0 * S1Q + C;
        double Spt = SPQ - S1P - S1Q + C;
        double r = 0.0;
        if (C > 0.0) {
            double num  = Spt - S1p * S1t / C;
            double varp = S2p - S1p * S1p / C;
            double vart = S2t - S1t * S1t / C;
            if (varp < 0.0) varp = 0.0;
            if (vart < 0.0) vart = 0.0;
            r = num / (sqrt(varp * vart) + 1e-6);
            r = fmin(1.0, fmax(-1.0, r));
        }
        double term_corr = sqrt(exp(r - 1.0));
        const double lw[5] = {0.1, 0.1, 0.2, 0.25, 0.35};
        double sc = 0.0;
#pragma unroll
        for (int l = 0; l < 5; l++) {
            // cumulative -> exclusive by differencing (exact in double)
            double ptot = sd[tt][6  + l] - ((l < 4) ? sd[tt][7  + l] : 0.0);
            double ttot = sd[tt][11 + l] - ((l < 4) ? sd[tt][12 + l] : 0.0);
            double hits = sd[tt][16 + l] - ((l < 4) ? sd[tt][17 + l] : 0.0);
            double maen = sd[tt][21 + l] - ((l < 4) ? sd[tt][22 + l] : 0.0);
            double ts  = hits / (ptot + ttot - hits + 1e-8);
            double mae = (ttot > 0.0) ? (maen / fmax(ttot, 1.0)) : 0.0;
            sc += lw[l] * ts * sqrt(exp(-mae / 100.0));
            sts[tt][l] = (float)ts;
            sma[tt][l] = (float)mae;
            out[41  + tt * 5 + l] = (float)ts;
            out[141 + tt * 5 + l] = (float)mae;
        }
        float sct = (float)(term_corr * sc);
        ssc[tt] = sct;
        out[1 + tt]  = sct;
        out[21 + tt] = (float)r;
    }
    __syncthreads();

    if (threadIdx.x < 5) {
        int l = threadIdx.x;
        float ts = 0.0f, ma = 0.0f;
#pragma unroll
        for (int tt = 0; tt < T_STEPS; tt++) { ts += sts[tt][l]; ma += sma[tt][l]; }
        out[241 + l] = ts / (float)T_STEPS;
        out[246 + l] = ma / (float)T_STEPS;
    }
    if (threadIdx.x == 5) {
        float tot = 0.0f;
#pragma unroll
        for (int tt = 0; tt < T_STEPS; tt++) tot += ssc[tt] * c_tw[tt];
        out[0] = tot;
    }
    if (threadIdx.x == 0) g_ticket = 0u;
}

extern "C" void kernel_launch(void* const* d_in, const int* in_sizes, int n_in,
                              void* d_out, int out_size) {
    const float* pred = (const float*)d_in[0];
    const float* targ = (const float*)d_in[1];
    const float* mask = (const float*)d_in[2];
    float* out = (float*)d_out;

    dim3 g1(NPB, T_STEPS);
    k_fused<<<g1, TPB>>>(pred, targ, mask, out);
}

// round 17
// speedup vs baseline: 1.0393x; 1.0393x over previous
#include <cuda_runtime.h>

#define T_STEPS 20
#define HW4 57600               // float4 per (b,t) slab
#define SLAB1OFF4 (20*HW4)      // float4 offset of batch-1 slab (same t)
#define NPB 22                  // 22*20 = 440 <= 444 = 148 SMs * 3 blocks: one wave
#define TPB 256
#define STRIDE (NPB*TPB)        // 5632 -> <=11 iters, <=88 elems/thread (<128: fields exact)
#define NACC 26
// g_part row: 0:cnt 1:S1P 2:S1Q 3:S2P 4:S2Q 5:SPQ (P=31^pn raw moments, nz-masked)
// 6..10:ptot_cum 11..15:ttot_cum 16..20:hits_cum 21..25:mae_cum

__device__ float        g_part[T_STEPS * NPB * NACC];
__device__ unsigned int g_ticket;

__constant__ float c_tw[T_STEPS] = {
    0.0075f, 0.02f, 0.03f, 0.04f, 0.05f, 0.06f, 0.07f, 0.08f, 0.09f, 0.1f,
    0.09f,   0.08f, 0.07f, 0.06f, 0.05f, 0.04f, 0.03f, 0.02f, 0.0075f, 0.005f};

// thresholds in normalized space: ln(1+thr)/ln(31)
#define C0 0.02775496f
#define C1 0.20184909f
#define C2 0.31992323f
#define C3 0.52177232f
#define C4 0.63984647f

// indicator(x >= C) as ONE SASS op: FFMA.SAT, result exactly 0.0f or 1.0f
// (x*2^40 - C*2^40 saturated to [0,1]; 2^40 makes x*BIG exact scaling)
#define BIGS 1099511627776.0f   // 2^40
__device__ __forceinline__ float indge(float x, float negCB) {
    float r;
    asm("fma.rn.sat.f32 %0, %1, 0f53800000, %2;" : "=f"(r) : "f"(x), "f"(negCB));
    return r;                    // 0f53800000 = 2^40
}

struct Acc {
    float cnt, s1p, s1t, s2p, s2t, spt;
    float ptA, ptB;   // packed cumulative ptot: A = l0 +128*l1 +16384*l2, B = l3 +128*l4
    float ttA, ttB;
    float hA,  hB;    // packed cumulative hits
    float m0, m1, m2, m3, m4;   // cumulative mae
};

__device__ __forceinline__ void accum_one(float pn, float tn, float mm, Acc& a) {
    const float K = 4.954196310386875f;   // log2(31)
    float P, Q;                           // P = 31^pn
    asm("ex2.approx.f32 %0, %1;" : "=f"(P) : "f"(pn * K));
    asm("ex2.approx.f32 %0, %1;" : "=f"(Q) : "f"(tn * K));

    // predicate-free sentinel: mm = (mk-0.5)*1e10
    // mk>0.5 -> mm >= 600 > pn -> min passes value; mk<=0.5 -> mm <= 0 -> fails all C_l
    float pnm = fminf(pn, mm);
    float tnm = fminf(tn, mm);

    // 10 indicators, each one FFMA.SAT (no FSETP/SEL, no predicate file)
    float a0 = indge(pnm, -(C0 * BIGS)), a1 = indge(pnm, -(C1 * BIGS)),
          a2 = indge(pnm, -(C2 * BIGS)), a3 = indge(pnm, -(C3 * BIGS)),
          a4 = indge(pnm, -(C4 * BIGS));
    float b0 = indge(tnm, -(C0 * BIGS)), b1 = indge(tnm, -(C1 * BIGS)),
          b2 = indge(tnm, -(C2 * BIGS)), b3 = indge(tnm, -(C3 * BIGS)),
          b4 = indge(tnm, -(C4 * BIGS));

    // packed indicator words (exact: fields <= 88 < 128, total < 2^24)
    float wpA = fmaf(a2, 16384.0f, fmaf(a1, 128.0f, a0));
    float wpB = fmaf(a4, 128.0f, a3);
    float wtA = fmaf(b2, 16384.0f, fmaf(b1, 128.0f, b0));
    float wtB = fmaf(b4, 128.0f, b3);
    a.ptA += wpA; a.ptB += wpB;
    a.ttA += wtA; a.ttB += wtB;

    // eq = (cp == ct): indicator-pair equality via bit tree (values are 0 / 0x3F800000)
    unsigned u01 = (__float_as_uint(a0) ^ __float_as_uint(b0))
                 | (__float_as_uint(a1) ^ __float_as_uint(b1));
    unsigned u23 = (__float_as_uint(a2) ^ __float_as_uint(b2))
                 | (__float_as_uint(a3) ^ __float_as_uint(b3));
    unsigned u   = u01 | u23 | (__float_as_uint(a4) ^ __float_as_uint(b4));
    float eq = 1.0f - __uint_as_float(u);      // u is 0 or 0x3F800000 (=1.0f)
    a.hA = fmaf(eq, wpA, a.hA);
    a.hB = fmaf(eq, wpB, a.hB);

    // nz = masked & not double-zero (bit-OR of 0/1.0f patterns)
    float orf = __uint_as_float(__float_as_uint(a0) | __float_as_uint(b0));
    float Pm = P * orf;
    float Qm = Q * orf;
    a.cnt += orf;
    a.s1p += Pm;
    a.s1t += Qm;
    a.s2p = fmaf(Pm, P, a.s2p);
    a.s2t = fmaf(Qm, Q, a.s2t);
    a.spt = fmaf(Pm, Q, a.spt);

    // cumulative mae (mask rides on b_l)
    float d = fabsf(P - Q);
    a.m0 = fmaf(b0, d, a.m0);
    a.m1 = fmaf(b1, d, a.m1);
    a.m2 = fmaf(b2, d, a.m2);
    a.m3 = fmaf(b3, d, a.m3);
    a.m4 = fmaf(b4, d, a.m4);
}

__device__ __forceinline__ void accum4(const float4& pv, const float4& tv,
                                       const float4& mv, Acc& a) {
    const float BIGM = 1.0e10f;
    accum_one(pv.x, tv.x, (mv.x - 0.5f) * BIGM, a);
    accum_one(pv.y, tv.y, (mv.y - 0.5f) * BIGM, a);
    accum_one(pv.z, tv.z, (mv.z - 0.5f) * BIGM, a);
    accum_one(pv.w, tv.w, (mv.w - 0.5f) * BIGM, a);
}

// exact unpack of base-128 packed integer-valued floats
__device__ __forceinline__ void unpack3(float v, float& c0, float& c1, float& c2) {
    c2 = floorf(v * (1.0f / 16384.0f));
    float rem = v - c2 * 16384.0f;
    c1 = floorf(rem * (1.0f / 128.0f));
    c0 = rem - c1 * 128.0f;
}
__device__ __forceinline__ void unpack2(float v, float& c0, float& c1) {
    c1 = floorf(v * (1.0f / 128.0f));
    c0 = v - c1 * 128.0f;
}

__global__ __launch_bounds__(TPB, 3) void k_fused(const float* __restrict__ pred,
                                                  const float* __restrict__ targ,
                                                  const float* __restrict__ mask,
                                                  float* __restrict__ out) {
    const int t   = blockIdx.y;
    const int gid = blockIdx.x * TPB + threadIdx.x;

    Acc a;
    a.cnt = a.s1p = a.s1t = a.s2p = a.s2t = a.spt = 0.0f;
    a.ptA = a.ptB = a.ttA = a.ttB = a.hA = a.hB = 0.0f;
    a.m0 = a.m1 = a.m2 = a.m3 = a.m4 = 0.0f;

    const size_t base4 = (size_t)t * HW4;
    const float4* p4  = (const float4*)pred + base4;
    const float4* t4  = (const float4*)targ + base4;
    const float4* m4  = (const float4*)mask + base4;
    const float4* p4b = p4 + SLAB1OFF4;
    const float4* t4b = t4 + SLAB1OFF4;
    const float4* m4b = m4 + SLAB1OFF4;

    // 1-deep, 6-load software pipeline (proven R9 skeleton)
    float4 pv0 = __ldcs(p4  + gid);
    float4 tv0 = __ldcs(t4  + gid);
    float4 mv0 = __ldcs(m4  + gid);
    float4 pv1 = __ldcs(p4b + gid);
    float4 tv1 = __ldcs(t4b + gid);
    float4 mv1 = __ldcs(m4b + gid);

#pragma unroll 1
    for (int v = gid + STRIDE; v < HW4; v += STRIDE) {
        float4 npv0 = __ldcs(p4  + v);
        float4 ntv0 = __ldcs(t4  + v);
        float4 nmv0 = __ldcs(m4  + v);
        float4 npv1 = __ldcs(p4b + v);
        float4 ntv1 = __ldcs(t4b + v);
        float4 nmv1 = __ldcs(m4b + v);
        accum4(pv0, tv0, mv0, a);
        accum4(pv1, tv1, mv1, a);
        pv0 = npv0; tv0 = ntv0; mv0 = nmv0;
        pv1 = npv1; tv1 = ntv1; mv1 = nmv1;
    }
    accum4(pv0, tv0, mv0, a);
    accum4(pv1, tv1, mv1, a);

    // unpack packed counters (exact) -> 26 partials
    float acc[NACC];
    acc[0] = a.cnt;
    acc[1] = a.s1p; acc[2] = a.s1t; acc[3] = a.s2p; acc[4] = a.s2t; acc[5] = a.spt;
    unpack3(a.ptA, acc[6],  acc[7],  acc[8]);  unpack2(a.ptB, acc[9],  acc[10]);
    unpack3(a.ttA, acc[11], acc[12], acc[13]); unpack2(a.ttB, acc[14], acc[15]);
    unpack3(a.hA,  acc[16], acc[17], acc[18]); unpack2(a.hB,  acc[19], acc[20]);
    acc[21] = a.m0; acc[22] = a.m1; acc[23] = a.m2; acc[24] = a.m3; acc[25] = a.m4;

    // deterministic warp tree reduce
#pragma unroll
    for (int i = 0; i < NACC; i++) {
#pragma unroll
        for (int o = 16; o > 0; o >>= 1)
            acc[i] += __shfl_xor_sync(0xffffffffu, acc[i], o);
    }

    __shared__ float s[TPB / 32][NACC];
    int w = threadIdx.x >> 5, ln = threadIdx.x & 31;
    if (ln == 0) {
#pragma unroll
        for (int i = 0; i < NACC; i++) s[w][i] = acc[i];
    }
    __syncthreads();
    if (threadIdx.x < NACC) {
        float vv = 0.0f;
#pragma unroll
        for (int w2 = 0; w2 < TPB / 32; w2++) vv += s[w2][threadIdx.x];
        g_part[((size_t)t * NPB + blockIdx.x) * NACC + threadIdx.x] = vv;
    }

    // ---- last block finishes (deterministic: reads fixed g_part) ----
    __threadfence();
    __syncthreads();
    __shared__ bool amLast;
    if (threadIdx.x == 0) {
        unsigned done = atomicAdd(&g_ticket, 1u);
        amLast = (done == (unsigned)(NPB * T_STEPS - 1));
    }
    __syncthreads();
    if (!amLast) return;
    __threadfence();

    __shared__ double sd[T_STEPS][NACC];
    for (int idx2 = threadIdx.x; idx2 < T_STEPS * NACC; idx2 += TPB) {
        int tt = idx2 / NACC, j = idx2 % NACC;
        double vv = 0.0;
#pragma unroll 11
        for (int k = 0; k < NPB; k++)
            vv += (double)g_part[((size_t)tt * NPB + k) * NACC + j];
        sd[tt][j] = vv;
    }
    __syncthreads();

    __shared__ float sts[T_STEPS][5], sma[T_STEPS][5], ssc[T_STEPS];
    if (threadIdx.x < T_STEPS) {
        int tt = threadIdx.x;
        double C   = sd[tt][0];
        double S1P = sd[tt][1], S1Q = sd[tt][2];
        double S2P = sd[tt][3], S2Q = sd[tt][4], SPQ = sd[tt][5];
        // shift: p = P-1, q = Q-1 on the nz-masked set of size C
        double S1p = S1P - C, S1t = S1Q - C;
        double S2p = S2P - 2.0 * S1P + C;
        double S2t = S2Q - 2.0 * S1Q + C;
        double Spt = SPQ - S1P - S1Q + C;
        double r = 0.0;
        if (C > 0.0) {
            double num  = Spt - S1p * S1t / C;
            double varp = S2p - S1p * S1p / C;
            double vart = S2t - S1t * S1t / C;
            if (varp < 0.0) varp = 0.0;
            if (vart < 0.0) vart = 0.0;
            r = num / (sqrt(varp * vart) + 1e-6);
            r = fmin(1.0, fmax(-1.0, r));
        }
        double term_corr = sqrt(exp(r - 1.0));
        const double lw[5] = {0.1, 0.1, 0.2, 0.25, 0.35};
        double sc = 0.0;
#pragma unroll
        for (int l = 0; l < 5; l++) {
            // cumulative -> exclusive by differencing (exact in double)
            double ptot = sd[tt][6  + l] - ((l < 4) ? sd[tt][7  + l] : 0.0);
            double ttot = sd[tt][11 + l] - ((l < 4) ? sd[tt][12 + l] : 0.0);
            double hits = sd[tt][16 + l] - ((l < 4) ? sd[tt][17 + l] : 0.0);
            double maen = sd[tt][21 + l] - ((l < 4) ? sd[tt][22 + l] : 0.0);
            double ts  = hits / (ptot + ttot - hits + 1e-8);
            double mae = (ttot > 0.0) ? (maen / fmax(ttot, 1.0)) : 0.0;
            sc += lw[l] * ts * sqrt(exp(-mae / 100.0));
            sts[tt][l] = (float)ts;
            sma[tt][l] = (float)mae;
            out[41  + tt * 5 + l] = (float)ts;
            out[141 + tt * 5 + l] = (float)mae;
        }
        float sct = (float)(term_corr * sc);
        ssc[tt] = sct;
        out[1 + tt]  = sct;
        out[21 + tt] = (float)r;
    }
    __syncthreads();

    if (threadIdx.x < 5) {
        int l = threadIdx.x;
        float ts = 0.0f, ma = 0.0f;
#pragma unroll
        for (int tt = 0; tt < T_STEPS; tt++) { ts += sts[tt][l]; ma += sma[tt][l]; }
        out[241 + l] = ts / (float)T_STEPS;
        out[246 + l] = ma / (float)T_STEPS;
    }
    if (threadIdx.x == 5) {
        float tot = 0.0f;
#pragma unroll
        for (int tt = 0; tt < T_STEPS; tt++) tot += ssc[tt] * c_tw[tt];
        out[0] = tot;
    }
    if (threadIdx.x == 0) g_ticket = 0u;
}

extern "C" void kernel_launch(void* const* d_in, const int* in_sizes, int n_in,
                              void* d_out, int out_size) {
    const float* pred = (const float*)d_in[0];
    const float* targ = (const float*)d_in[1];
    const float* mask = (const float*)d_in[2];
    float* out = (float*)d_out;

    dim3 g1(NPB, T_STEPS);
    k_fused<<<g1, TPB>>>(pred, targ, mask, out);
}